// round 2
// baseline (speedup 1.0000x reference)
#include <cuda_runtime.h>
#include <math.h>

#define BB 4
#define NN 2048
#define DIMM 1024
#define HH 16
#define DHH 64
#define SCALE 0.125f

// Scratch: ZTU and SSA in [B, H, N, DH] layout.
__device__ float g_ztu[BB * HH * NN * DHH];
__device__ float g_ssa[BB * HH * NN * DHH];

// ---------------------------------------------------------------------------
// GEMM1: C[m,k] = sum_c ZT[m,c] * W[k,c]   (m = b*N+n, k = h*64+d)
// scatter into g_ztu[b,h,n,d]
// 64x64 tile, BK=16, 256 threads, 4x4 micro-tile.
// ---------------------------------------------------------------------------
__global__ __launch_bounds__(256)
void gemm1_kernel(const float* __restrict__ ZT, const float* __restrict__ W) {
    __shared__ float As[16][68];  // As[kk][m]
    __shared__ float Bs[16][68];  // Bs[kk][k]
    const int bm = blockIdx.y * 64;
    const int bn = blockIdx.x * 64;
    const int tid = threadIdx.x;
    const int tx = tid & 15, ty = tid >> 4;

    float acc[4][4];
#pragma unroll
    for (int i = 0; i < 4; i++)
#pragma unroll
        for (int j = 0; j < 4; j++) acc[i][j] = 0.f;

    for (int k0 = 0; k0 < DIMM; k0 += 16) {
#pragma unroll
        for (int i = 0; i < 4; i++) {
            int idx = tid + i * 256;         // 0..1023 over 64 rows x 16 cols
            int r = idx >> 4, c = idx & 15;
            As[c][r] = ZT[(size_t)(bm + r) * DIMM + k0 + c];
            Bs[c][r] = W[(size_t)(bn + r) * DIMM + k0 + c];
        }
        __syncthreads();
#pragma unroll
        for (int kk = 0; kk < 16; kk++) {
            float4 a = *(const float4*)(&As[kk][ty * 4]);
            float4 b = *(const float4*)(&Bs[kk][tx * 4]);
            float av[4] = {a.x, a.y, a.z, a.w};
            float bv[4] = {b.x, b.y, b.z, b.w};
#pragma unroll
            for (int i = 0; i < 4; i++)
#pragma unroll
                for (int j = 0; j < 4; j++) acc[i][j] += av[i] * bv[j];
        }
        __syncthreads();
    }
#pragma unroll
    for (int i = 0; i < 4; i++) {
        int m = bm + ty * 4 + i;
        int b = m / NN, n = m % NN;
#pragma unroll
        for (int j = 0; j < 4; j++) {
            int k = bn + tx * 4 + j;
            int h = k >> 6, d = k & 63;
            g_ztu[(((size_t)(b * HH + h) * NN + n) * DHH) + d] = acc[i][j];
        }
    }
}

// ---------------------------------------------------------------------------
// Flash attention per (b,h): out[b,h,n,d]; Q=K=V=g_ztu slice.
// Block: 64 query rows, 256 threads. Thread (r = tid/4, q = tid%4).
// Each thread: S for j = q+4*jj (16 vals); O dims d = 16c + 4q + dd (16 vals).
// ---------------------------------------------------------------------------
__global__ __launch_bounds__(256)
void attn_kernel() {
    const int bh = blockIdx.y;
    const int q0 = blockIdx.x * 64;
    const float* __restrict__ base = g_ztu + (size_t)bh * NN * DHH;
    float* __restrict__ outb = g_ssa + (size_t)bh * NN * DHH;

    __shared__ float Ts[64][68];   // K/V tile (same data, Q=K=V)
    __shared__ float QPs[64][68];  // Q tile, then reused as P

    const int tid = threadIdx.x;
    const int r = tid >> 2;
    const int q = tid & 3;

    // Load Q tile (float4).
    for (int i = tid; i < 64 * 16; i += 256) {
        int rr = i >> 4, c4 = i & 15;
        *(float4*)(&QPs[rr][c4 * 4]) =
            *(const float4*)(base + (size_t)(q0 + rr) * DHH + c4 * 4);
    }
    __syncthreads();

    float qreg[64];
#pragma unroll
    for (int d = 0; d < 64; d++) qreg[d] = QPs[r][d] * SCALE;

    float m_run = -INFINITY, l_run = 0.f;
    float acc[16];
#pragma unroll
    for (int i = 0; i < 16; i++) acc[i] = 0.f;

    for (int j0 = 0; j0 < NN; j0 += 64) {
        __syncthreads();  // protect prior Ts reads & qreg reads
        for (int i = tid; i < 64 * 16; i += 256) {
            int rr = i >> 4, c4 = i & 15;
            *(float4*)(&Ts[rr][c4 * 4]) =
                *(const float4*)(base + (size_t)(j0 + rr) * DHH + c4 * 4);
        }
        __syncthreads();

        // S: s[jj] = q_row . T[q + 4*jj]
        float s[16];
        float tmax = -INFINITY;
#pragma unroll
        for (int jj = 0; jj < 16; jj++) {
            int j = q + 4 * jj;
            float sv = 0.f;
#pragma unroll
            for (int d4 = 0; d4 < 16; d4++) {
                float4 t = *(const float4*)(&Ts[j][d4 * 4]);
                sv += qreg[d4 * 4 + 0] * t.x + qreg[d4 * 4 + 1] * t.y +
                      qreg[d4 * 4 + 2] * t.z + qreg[d4 * 4 + 3] * t.w;
            }
            s[jj] = sv;
            tmax = fmaxf(tmax, sv);
        }
        // row-max across the 4-lane quad
        tmax = fmaxf(tmax, __shfl_xor_sync(0xffffffffu, tmax, 1));
        tmax = fmaxf(tmax, __shfl_xor_sync(0xffffffffu, tmax, 2));

        float m_new = fmaxf(m_run, tmax);
        float alpha = __expf(m_run - m_new);
        float lsum = 0.f;
#pragma unroll
        for (int jj = 0; jj < 16; jj++) {
            float p = __expf(s[jj] - m_new);
            lsum += p;
            QPs[r][q + 4 * jj] = p;
        }
        lsum += __shfl_xor_sync(0xffffffffu, lsum, 1);
        lsum += __shfl_xor_sync(0xffffffffu, lsum, 2);
        l_run = l_run * alpha + lsum;
        m_run = m_new;
#pragma unroll
        for (int i = 0; i < 16; i++) acc[i] *= alpha;

        __syncwarp();  // P produced/consumed within the same quad's warp

        // O += P * V  (V tile == Ts)
#pragma unroll 4
        for (int j = 0; j < 64; j++) {
            float p = QPs[r][j];
#pragma unroll
            for (int c = 0; c < 4; c++) {
                float4 t = *(const float4*)(&Ts[j][16 * c + 4 * q]);
                acc[c * 4 + 0] += p * t.x;
                acc[c * 4 + 1] += p * t.y;
                acc[c * 4 + 2] += p * t.z;
                acc[c * 4 + 3] += p * t.w;
            }
        }
    }

    float inv_l = 1.0f / l_run;
    float* orow = outb + (size_t)(q0 + r) * DHH;
#pragma unroll
    for (int c = 0; c < 4; c++) {
        float4 v = make_float4(acc[c * 4 + 0] * inv_l, acc[c * 4 + 1] * inv_l,
                               acc[c * 4 + 2] * inv_l, acc[c * 4 + 3] * inv_l);
        *(float4*)(orow + 16 * c + 4 * q) = v;
    }
}

// ---------------------------------------------------------------------------
// GEMM2: out[m,c] = sum_k SSA[m,k] * W[k,c]
// SSA[m,k] gathered from g_ssa[b,h,n,d] (k = h*64+d; BK=16 divides 64, so
// each k-tile stays inside one head -> contiguous d loads).
// ---------------------------------------------------------------------------
__global__ __launch_bounds__(256)
void gemm2_kernel(const float* __restrict__ W, float* __restrict__ out) {
    __shared__ float As[16][68];  // As[kk][m]
    __shared__ float Bs[16][68];  // Bs[kk][c]
    const int bm = blockIdx.y * 64;
    const int bc = blockIdx.x * 64;
    const int tid = threadIdx.x;
    const int tx = tid & 15, ty = tid >> 4;

    float acc[4][4];
#pragma unroll
    for (int i = 0; i < 4; i++)
#pragma unroll
        for (int j = 0; j < 4; j++) acc[i][j] = 0.f;

    for (int k0 = 0; k0 < DIMM; k0 += 16) {
        int h = k0 >> 6;
        int dbase = k0 & 63;
#pragma unroll
        for (int i = 0; i < 4; i++) {
            int idx = tid + i * 256;
            // A tile: 64 rows(m) x 16 cols(k)
            int r = idx >> 4, c = idx & 15;
            int m = bm + r;
            int b = m / NN, n = m % NN;
            As[c][r] = g_ssa[((size_t)(b * HH + h) * NN + n) * DHH + dbase + c];
            // B tile: 16 rows(k) x 64 cols(c), c contiguous
            int kk = idx >> 6, cc = idx & 63;
            Bs[kk][cc] = W[(size_t)(k0 + kk) * DIMM + bc + cc];
        }
        __syncthreads();
#pragma unroll
        for (int kk = 0; kk < 16; kk++) {
            float4 a = *(const float4*)(&As[kk][ty * 4]);
            float4 b = *(const float4*)(&Bs[kk][tx * 4]);
            float av[4] = {a.x, a.y, a.z, a.w};
            float bv[4] = {b.x, b.y, b.z, b.w};
#pragma unroll
            for (int i = 0; i < 4; i++)
#pragma unroll
                for (int j = 0; j < 4; j++) acc[i][j] += av[i] * bv[j];
        }
        __syncthreads();
    }
#pragma unroll
    for (int i = 0; i < 4; i++) {
        int m = bm + ty * 4 + i;
#pragma unroll
        for (int j = 0; j < 4; j++) {
            out[(size_t)m * DIMM + bc + tx * 4 + j] = acc[i][j];
        }
    }
}

extern "C" void kernel_launch(void* const* d_in, const int* in_sizes, int n_in,
                              void* d_out, int out_size) {
    const float* ZT = (const float*)d_in[0];   // [B, N, DIM]
    const float* W  = (const float*)d_in[1];   // [H*DH, DIM]
    float* out = (float*)d_out;                // [B, N, DIM]
    (void)in_sizes; (void)n_in; (void)out_size;

    dim3 gsz(DIMM / 64, (BB * NN) / 64);       // 16 x 128
    gemm1_kernel<<<gsz, 256>>>(ZT, W);
    dim3 asz(NN / 64, BB * HH);                // 32 x 64
    attn_kernel<<<asz, 256>>>();
    gemm2_kernel<<<gsz, 256>>>(W, out);
}

// round 4
// speedup vs baseline: 4.5021x; 4.5021x over previous
#include <cuda_runtime.h>
#include <cuda_fp16.h>
#include <stdint.h>
#include <math.h>

#define BB 4
#define NN 2048
#define DIMM 1024
#define HH 16
#define DHH 64
#define SCALE 0.125f
#define MTOT (BB * NN) /* 8192 */
#define S72 72         /* smem row stride in fp16 (144 B, conflict-free ldmatrix) */

// ---------------- fp16 hi/lo split scratch ---------------------------------
__device__ __half g_zt_hi[MTOT * DIMM], g_zt_lo[MTOT * DIMM];    // [m, c]
__device__ __half g_w_hi[DIMM * DIMM], g_w_lo[DIMM * DIMM];      // [kp, c]
__device__ __half g_wt_hi[DIMM * DIMM], g_wt_lo[DIMM * DIMM];    // [c, kp]
__device__ __half g_ztu_hi[MTOT * DIMM], g_ztu_lo[MTOT * DIMM];  // [bh, n, d]
__device__ __half g_ssa_hi[MTOT * DIMM], g_ssa_lo[MTOT * DIMM];  // [m, k]

// ---------------- helpers ---------------------------------------------------
__device__ __forceinline__ uint32_t smem_u32(const void* p) {
    uint32_t a;
    asm("{ .reg .u64 t; cvta.to.shared.u64 t, %1; cvt.u32.u64 %0, t; }" : "=r"(a) : "l"(p));
    return a;
}
__device__ __forceinline__ void ldsm4(uint32_t& r0, uint32_t& r1, uint32_t& r2, uint32_t& r3,
                                      uint32_t addr) {
    asm volatile("ldmatrix.sync.aligned.m8n8.x4.shared.b16 {%0,%1,%2,%3},[%4];"
                 : "=r"(r0), "=r"(r1), "=r"(r2), "=r"(r3) : "r"(addr));
}
__device__ __forceinline__ void ldsm4t(uint32_t& r0, uint32_t& r1, uint32_t& r2, uint32_t& r3,
                                       uint32_t addr) {
    asm volatile("ldmatrix.sync.aligned.m8n8.x4.trans.shared.b16 {%0,%1,%2,%3},[%4];"
                 : "=r"(r0), "=r"(r1), "=r"(r2), "=r"(r3) : "r"(addr));
}
__device__ __forceinline__ void mma16816(float* c, const uint32_t* a, uint32_t b0, uint32_t b1) {
    asm volatile(
        "mma.sync.aligned.m16n8k16.row.col.f32.f16.f16.f32 "
        "{%0,%1,%2,%3},{%4,%5,%6,%7},{%8,%9},{%0,%1,%2,%3};"
        : "+f"(c[0]), "+f"(c[1]), "+f"(c[2]), "+f"(c[3])
        : "r"(a[0]), "r"(a[1]), "r"(a[2]), "r"(a[3]), "r"(b0), "r"(b1));
}
__device__ __forceinline__ uint32_t pkh(__half a, __half b) {
    return (uint32_t)__half_as_ushort(a) | ((uint32_t)__half_as_ushort(b) << 16);
}
// split two fp32 into packed fp16 hi and lo words
__device__ __forceinline__ void split2(float x, float y, uint32_t& hi, uint32_t& lo) {
    __half hx = __float2half_rn(x), hy = __float2half_rn(y);
    hi = pkh(hx, hy);
    lo = pkh(__float2half_rn(x - __half2float(hx)), __float2half_rn(y - __half2float(hy)));
}

// ---------------- split kernels ---------------------------------------------
__global__ __launch_bounds__(256) void split_zt_kernel(const float* __restrict__ ZT) {
    size_t i = ((size_t)blockIdx.x * blockDim.x + threadIdx.x) * 4;
    float4 v = *(const float4*)(ZT + i);
    uint32_t h0, l0, h1, l1;
    split2(v.x, v.y, h0, l0);
    split2(v.z, v.w, h1, l1);
    *(uint2*)&g_zt_hi[i] = make_uint2(h0, h1);
    *(uint2*)&g_zt_lo[i] = make_uint2(l0, l1);
}

__global__ __launch_bounds__(1024) void split_w_kernel(const float* __restrict__ W) {
    __shared__ float t[32][33];
    int tx = threadIdx.x, ty = threadIdx.y;
    int k = blockIdx.y * 32 + ty, c = blockIdx.x * 32 + tx;
    float v = W[(size_t)k * DIMM + c];
    __half h = __float2half_rn(v);
    g_w_hi[(size_t)k * DIMM + c] = h;
    g_w_lo[(size_t)k * DIMM + c] = __float2half_rn(v - __half2float(h));
    t[ty][tx] = v;
    __syncthreads();
    int k2 = blockIdx.y * 32 + tx, c2 = blockIdx.x * 32 + ty;
    float v2 = t[tx][ty];
    __half h2 = __float2half_rn(v2);
    g_wt_hi[(size_t)c2 * DIMM + k2] = h2;
    g_wt_lo[(size_t)c2 * DIMM + k2] = __float2half_rn(v2 - __half2float(h2));
}

// ---------------- HMMA GEMM -------------------------------------------------
// C[128x128 tile] = A[128,1024] · B[128,1024]^T, fp16 hi/lo 3-term, fp32 acc.
// MODE 0: A=zt, B=w  -> split-write g_ztu ([bh,n,d] scatter)
// MODE 1: A=ssa, B=wt -> fp32 out
template <int MODE>
__global__ __launch_bounds__(256) void gemm_hmma(float* __restrict__ outp) {
    extern __shared__ char sm[];
    __half* sAh = (__half*)sm;
    __half* sAl = sAh + 128 * S72;
    __half* sBh = sAl + 128 * S72;
    __half* sBl = sBh + 128 * S72;
    const uint32_t aAh = smem_u32(sAh), aAl = smem_u32(sAl);
    const uint32_t aBh = smem_u32(sBh), aBl = smem_u32(sBl);

    const int tid = threadIdx.x, lane = tid & 31, wid = tid >> 5;
    const int wm = wid & 3, wn = wid >> 2;
    const int bm = blockIdx.y * 128, bn = blockIdx.x * 128;

    const __half* Agh = (MODE == 0) ? g_zt_hi : g_ssa_hi;
    const __half* Agl = (MODE == 0) ? g_zt_lo : g_ssa_lo;
    const __half* Bgh = (MODE == 0) ? g_w_hi : g_wt_hi;
    const __half* Bgl = (MODE == 0) ? g_w_lo : g_wt_lo;

    float c[2][8][4];
#pragma unroll
    for (int mi = 0; mi < 2; mi++)
#pragma unroll
        for (int nb = 0; nb < 8; nb++)
#pragma unroll
            for (int q = 0; q < 4; q++) c[mi][nb][q] = 0.f;

    for (int ch = 0; ch < 16; ch++) {
        const int k0 = ch * 64;
#pragma unroll
        for (int i = 0; i < 4; i++) {
            int idx = tid + i * 256;
            int r = idx >> 3, cc = (idx & 7) * 8;
            *(uint4*)(sAh + r * S72 + cc) = *(const uint4*)(Agh + (size_t)(bm + r) * DIMM + k0 + cc);
            *(uint4*)(sAl + r * S72 + cc) = *(const uint4*)(Agl + (size_t)(bm + r) * DIMM + k0 + cc);
            *(uint4*)(sBh + r * S72 + cc) = *(const uint4*)(Bgh + (size_t)(bn + r) * DIMM + k0 + cc);
            *(uint4*)(sBl + r * S72 + cc) = *(const uint4*)(Bgl + (size_t)(bn + r) * DIMM + k0 + cc);
        }
        __syncthreads();
#pragma unroll
        for (int kd = 0; kd < 4; kd++) {
            const uint32_t colb = (kd * 16 + ((lane >> 4) << 3)) * 2;
            uint32_t ah[2][4], al[2][4];
#pragma unroll
            for (int mi = 0; mi < 2; mi++) {
                uint32_t ro = (uint32_t)(wm * 32 + mi * 16 + (lane & 15)) * 144 + colb;
                ldsm4(ah[mi][0], ah[mi][1], ah[mi][2], ah[mi][3], aAh + ro);
                ldsm4(al[mi][0], al[mi][1], al[mi][2], al[mi][3], aAl + ro);
            }
            uint32_t bh[8][2], bl[8][2];
#pragma unroll
            for (int np = 0; np < 4; np++) {
                uint32_t ro = (uint32_t)(wn * 64 + np * 16 + (lane & 15)) * 144 + colb;
                uint32_t r0, r1, r2, r3;
                ldsm4(r0, r1, r2, r3, aBh + ro);
                bh[np * 2][0] = r0; bh[np * 2][1] = r2;
                bh[np * 2 + 1][0] = r1; bh[np * 2 + 1][1] = r3;
                ldsm4(r0, r1, r2, r3, aBl + ro);
                bl[np * 2][0] = r0; bl[np * 2][1] = r2;
                bl[np * 2 + 1][0] = r1; bl[np * 2 + 1][1] = r3;
            }
#pragma unroll
            for (int mi = 0; mi < 2; mi++)
#pragma unroll
                for (int nb = 0; nb < 8; nb++) {
                    mma16816(c[mi][nb], ah[mi], bh[nb][0], bh[nb][1]);
                    mma16816(c[mi][nb], ah[mi], bl[nb][0], bl[nb][1]);
                    mma16816(c[mi][nb], al[mi], bh[nb][0], bh[nb][1]);
                }
        }
        __syncthreads();
    }

    // epilogue
#pragma unroll
    for (int mi = 0; mi < 2; mi++) {
        const int m0 = bm + wm * 32 + mi * 16 + (lane >> 2);
#pragma unroll
        for (int nb = 0; nb < 8; nb++) {
            const int col = bn + wn * 64 + nb * 8 + 2 * (lane & 3);
            if (MODE == 0) {
                const int h = col >> 6, d = col & 63;
#pragma unroll
                for (int rr = 0; rr < 2; rr++) {
                    int m = m0 + rr * 8;
                    int b = m >> 11, n = m & 2047;
                    size_t base = (((size_t)(b * HH + h) * NN) + n) * DHH + d;
                    uint32_t hi, lo;
                    split2(c[mi][nb][rr * 2], c[mi][nb][rr * 2 + 1], hi, lo);
                    *(uint32_t*)&g_ztu_hi[base] = hi;
                    *(uint32_t*)&g_ztu_lo[base] = lo;
                }
            } else {
                *(float2*)&outp[(size_t)m0 * DIMM + col] = make_float2(c[mi][nb][0], c[mi][nb][1]);
                *(float2*)&outp[(size_t)(m0 + 8) * DIMM + col] = make_float2(c[mi][nb][2], c[mi][nb][3]);
            }
        }
    }
}

// ---------------- HMMA flash attention --------------------------------------
// CTA: 128 q rows of one (b,h); 8 warps x m16; key chunks of 64. Q=K=V.
__global__ __launch_bounds__(256) void attn_hmma() {
    extern __shared__ char sm[];
    __half* sQh = (__half*)sm;
    __half* sQl = sQh + 128 * S72;
    __half* sKh = sQl + 128 * S72;
    __half* sKl = sKh + 64 * S72;
    const uint32_t aQh = smem_u32(sQh), aQl = smem_u32(sQl);
    const uint32_t aKh = smem_u32(sKh), aKl = smem_u32(sKl);

    const int tid = threadIdx.x, lane = tid & 31, wid = tid >> 5;
    const int bh = blockIdx.y, q0 = blockIdx.x * 128;
    const __half* zh = g_ztu_hi + (size_t)bh * NN * DHH;
    const __half* zl = g_ztu_lo + (size_t)bh * NN * DHH;

    // Q tile -> smem -> frags (held whole kernel)
#pragma unroll
    for (int i = 0; i < 4; i++) {
        int idx = tid + i * 256;
        int r = idx >> 3, cc = (idx & 7) * 8;
        *(uint4*)(sQh + r * S72 + cc) = *(const uint4*)(zh + (size_t)(q0 + r) * DHH + cc);
        *(uint4*)(sQl + r * S72 + cc) = *(const uint4*)(zl + (size_t)(q0 + r) * DHH + cc);
    }
    __syncthreads();

    uint32_t qh[4][4], ql[4][4];
#pragma unroll
    for (int kd = 0; kd < 4; kd++) {
        uint32_t ro = (uint32_t)(wid * 16 + (lane & 15)) * 144 + (kd * 16 + ((lane >> 4) << 3)) * 2;
        ldsm4(qh[kd][0], qh[kd][1], qh[kd][2], qh[kd][3], aQh + ro);
        ldsm4(ql[kd][0], ql[kd][1], ql[kd][2], ql[kd][3], aQl + ro);
    }

    float o[8][4];
#pragma unroll
    for (int nb = 0; nb < 8; nb++)
#pragma unroll
        for (int q = 0; q < 4; q++) o[nb][q] = 0.f;
    float mr0 = -INFINITY, mr1 = -INFINITY, l0 = 0.f, l1 = 0.f;

    for (int j0 = 0; j0 < NN; j0 += 64) {
        __syncthreads();  // prior chunk's V reads complete
#pragma unroll
        for (int i = 0; i < 2; i++) {
            int idx = tid + i * 256;
            int r = idx >> 3, cc = (idx & 7) * 8;
            *(uint4*)(sKh + r * S72 + cc) = *(const uint4*)(zh + (size_t)(j0 + r) * DHH + cc);
            *(uint4*)(sKl + r * S72 + cc) = *(const uint4*)(zl + (size_t)(j0 + r) * DHH + cc);
        }
        __syncthreads();

        // S = Q K^T (16 x 64 per warp)
        float s[8][4];
#pragma unroll
        for (int nb = 0; nb < 8; nb++)
#pragma unroll
            for (int q = 0; q < 4; q++) s[nb][q] = 0.f;
#pragma unroll
        for (int kd = 0; kd < 4; kd++) {
            const uint32_t colb = (kd * 16 + ((lane >> 4) << 3)) * 2;
            uint32_t bhf[8][2], blf[8][2];
#pragma unroll
            for (int np = 0; np < 4; np++) {
                uint32_t ro = (uint32_t)(np * 16 + (lane & 15)) * 144 + colb;
                uint32_t r0, r1, r2, r3;
                ldsm4(r0, r1, r2, r3, aKh + ro);
                bhf[np * 2][0] = r0; bhf[np * 2][1] = r2;
                bhf[np * 2 + 1][0] = r1; bhf[np * 2 + 1][1] = r3;
                ldsm4(r0, r1, r2, r3, aKl + ro);
                blf[np * 2][0] = r0; blf[np * 2][1] = r2;
                blf[np * 2 + 1][0] = r1; blf[np * 2 + 1][1] = r3;
            }
#pragma unroll
            for (int nb = 0; nb < 8; nb++) {
                mma16816(s[nb], qh[kd], bhf[nb][0], bhf[nb][1]);
                mma16816(s[nb], qh[kd], blf[nb][0], blf[nb][1]);
                mma16816(s[nb], ql[kd], bhf[nb][0], bhf[nb][1]);
            }
        }

        // softmax (rows r=lane/4 and r+8)
        float t0 = -INFINITY, t1 = -INFINITY;
#pragma unroll
        for (int nb = 0; nb < 8; nb++) {
#pragma unroll
            for (int q = 0; q < 4; q++) s[nb][q] *= SCALE;
            t0 = fmaxf(t0, fmaxf(s[nb][0], s[nb][1]));
            t1 = fmaxf(t1, fmaxf(s[nb][2], s[nb][3]));
        }
        t0 = fmaxf(t0, __shfl_xor_sync(0xffffffffu, t0, 1));
        t0 = fmaxf(t0, __shfl_xor_sync(0xffffffffu, t0, 2));
        t1 = fmaxf(t1, __shfl_xor_sync(0xffffffffu, t1, 1));
        t1 = fmaxf(t1, __shfl_xor_sync(0xffffffffu, t1, 2));
        float mn0 = fmaxf(mr0, t0), mn1 = fmaxf(mr1, t1);
        float al0 = __expf(mr0 - mn0), al1 = __expf(mr1 - mn1);
        float ls0 = 0.f, ls1 = 0.f;
#pragma unroll
        for (int nb = 0; nb < 8; nb++) {
            s[nb][0] = __expf(s[nb][0] - mn0);
            s[nb][1] = __expf(s[nb][1] - mn0);
            s[nb][2] = __expf(s[nb][2] - mn1);
            s[nb][3] = __expf(s[nb][3] - mn1);
            ls0 += s[nb][0] + s[nb][1];
            ls1 += s[nb][2] + s[nb][3];
        }
        ls0 += __shfl_xor_sync(0xffffffffu, ls0, 1);
        ls0 += __shfl_xor_sync(0xffffffffu, ls0, 2);
        ls1 += __shfl_xor_sync(0xffffffffu, ls1, 1);
        ls1 += __shfl_xor_sync(0xffffffffu, ls1, 2);
        l0 = l0 * al0 + ls0;
        l1 = l1 * al1 + ls1;
        mr0 = mn0;
        mr1 = mn1;
#pragma unroll
        for (int nb = 0; nb < 8; nb++) {
            o[nb][0] *= al0; o[nb][1] *= al0;
            o[nb][2] *= al1; o[nb][3] *= al1;
        }

        // O += P V  (P from s frags; V = same K tile, ldmatrix.trans)
#pragma unroll
        for (int kj = 0; kj < 4; kj++) {
            uint32_t pah[4], pal[4];
            split2(s[2 * kj][0], s[2 * kj][1], pah[0], pal[0]);
            split2(s[2 * kj][2], s[2 * kj][3], pah[1], pal[1]);
            split2(s[2 * kj + 1][0], s[2 * kj + 1][1], pah[2], pal[2]);
            split2(s[2 * kj + 1][2], s[2 * kj + 1][3], pah[3], pal[3]);

            const uint32_t colb = ((lane >> 4) << 3) * 2;
            uint32_t vh[8][2], vl[8][2];
#pragma unroll
            for (int dp = 0; dp < 4; dp++) {
                uint32_t ro = (uint32_t)(kj * 16 + (lane & 15)) * 144 + dp * 32 + colb;
                uint32_t r0, r1, r2, r3;
                ldsm4t(r0, r1, r2, r3, aKh + ro);
                vh[dp * 2][0] = r0; vh[dp * 2][1] = r1;
                vh[dp * 2 + 1][0] = r2; vh[dp * 2 + 1][1] = r3;
                ldsm4t(r0, r1, r2, r3, aKl + ro);
                vl[dp * 2][0] = r0; vl[dp * 2][1] = r1;
                vl[dp * 2 + 1][0] = r2; vl[dp * 2 + 1][1] = r3;
            }
#pragma unroll
            for (int db = 0; db < 8; db++) {
                mma16816(o[db], pah, vh[db][0], vh[db][1]);
                mma16816(o[db], pah, vl[db][0], vl[db][1]);
                mma16816(o[db], pal, vh[db][0], vh[db][1]);
            }
        }
    }

    // epilogue -> ssa hi/lo [b, n, h*64+d]
    const float inv0 = 1.f / l0, inv1 = 1.f / l1;
    const int b = bh >> 4, h = bh & 15;
    const int r0w = q0 + wid * 16 + (lane >> 2);
#pragma unroll
    for (int db = 0; db < 8; db++) {
        const int d = db * 8 + 2 * (lane & 3);
        size_t base0 = ((size_t)b * NN + r0w) * DIMM + h * DHH + d;
        size_t base1 = ((size_t)b * NN + r0w + 8) * DIMM + h * DHH + d;
        uint32_t hi, lo;
        split2(o[db][0] * inv0, o[db][1] * inv0, hi, lo);
        *(uint32_t*)&g_ssa_hi[base0] = hi;
        *(uint32_t*)&g_ssa_lo[base0] = lo;
        split2(o[db][2] * inv1, o[db][3] * inv1, hi, lo);
        *(uint32_t*)&g_ssa_hi[base1] = hi;
        *(uint32_t*)&g_ssa_lo[base1] = lo;
    }
}

// ---------------- launch -----------------------------------------------------
#define GEMM_SMEM (4 * 128 * S72 * 2)                    /* 73728 B */
#define ATTN_SMEM ((2 * 128 + 2 * 64) * S72 * 2)         /* 55296 B */

extern "C" void kernel_launch(void* const* d_in, const int* in_sizes, int n_in,
                              void* d_out, int out_size) {
    const float* ZT = (const float*)d_in[0];  // [B, N, DIM]
    const float* W = (const float*)d_in[1];   // [H*DH, DIM]
    float* out = (float*)d_out;               // [B, N, DIM]
    (void)in_sizes; (void)n_in; (void)out_size;

    cudaFuncSetAttribute(gemm_hmma<0>, cudaFuncAttributeMaxDynamicSharedMemorySize, GEMM_SMEM);
    cudaFuncSetAttribute(gemm_hmma<1>, cudaFuncAttributeMaxDynamicSharedMemorySize, GEMM_SMEM);
    cudaFuncSetAttribute(attn_hmma, cudaFuncAttributeMaxDynamicSharedMemorySize, ATTN_SMEM);

    split_zt_kernel<<<(MTOT * DIMM) / (256 * 4), 256>>>(ZT);
    split_w_kernel<<<dim3(32, 32), dim3(32, 32)>>>(W);
    gemm_hmma<0><<<dim3(DIMM / 128, MTOT / 128), 256, GEMM_SMEM>>>(nullptr);
    attn_hmma<<<dim3(NN / 128, BB * HH), 256, ATTN_SMEM>>>();
    gemm_hmma<1><<<dim3(DIMM / 128, MTOT / 128), 256, GEMM_SMEM>>>(out);
}

// round 6
// speedup vs baseline: 5.5355x; 1.2296x over previous
#include <cuda_runtime.h>
#include <cuda_fp16.h>
#include <stdint.h>
#include <math.h>

#define BB 4
#define NN 2048
#define DIMM 1024
#define HH 16
#define DHH 64
#define SCALE 0.125f
#define MTOT (BB * NN) /* 8192 */
#define S72 72         /* smem row stride in fp16 (144 B, conflict-free ldmatrix) */

// ---------------- fp16 hi/lo split scratch ---------------------------------
__device__ __half g_zt_hi[MTOT * DIMM], g_zt_lo[MTOT * DIMM];    // [m, c]
__device__ __half g_w_hi[DIMM * DIMM], g_w_lo[DIMM * DIMM];      // [kp, c]
__device__ __half g_wt_hi[DIMM * DIMM], g_wt_lo[DIMM * DIMM];    // [c, kp]
__device__ __half g_ztu_hi[MTOT * DIMM], g_ztu_lo[MTOT * DIMM];  // [bh, n, d]
__device__ __half g_ssa_hi[MTOT * DIMM], g_ssa_lo[MTOT * DIMM];  // [m, k]

// ---------------- helpers ---------------------------------------------------
__device__ __forceinline__ uint32_t smem_u32(const void* p) {
    uint32_t a;
    asm("{ .reg .u64 t; cvta.to.shared.u64 t, %1; cvt.u32.u64 %0, t; }" : "=r"(a) : "l"(p));
    return a;
}
__device__ __forceinline__ void cp16(uint32_t dst, const void* src) {
    asm volatile("cp.async.cg.shared.global [%0], [%1], 16;" :: "r"(dst), "l"(src));
}
#define CP_COMMIT() asm volatile("cp.async.commit_group;" ::: "memory")
#define CP_WAIT1() asm volatile("cp.async.wait_group 1;" ::: "memory")
#define CP_WAIT0() asm volatile("cp.async.wait_group 0;" ::: "memory")

__device__ __forceinline__ void ldsm4(uint32_t& r0, uint32_t& r1, uint32_t& r2, uint32_t& r3,
                                      uint32_t addr) {
    asm volatile("ldmatrix.sync.aligned.m8n8.x4.shared.b16 {%0,%1,%2,%3},[%4];"
                 : "=r"(r0), "=r"(r1), "=r"(r2), "=r"(r3) : "r"(addr));
}
__device__ __forceinline__ void ldsm4t(uint32_t& r0, uint32_t& r1, uint32_t& r2, uint32_t& r3,
                                       uint32_t addr) {
    asm volatile("ldmatrix.sync.aligned.m8n8.x4.trans.shared.b16 {%0,%1,%2,%3},[%4];"
                 : "=r"(r0), "=r"(r1), "=r"(r2), "=r"(r3) : "r"(addr));
}
__device__ __forceinline__ void mma16816(float* c, const uint32_t* a, uint32_t b0, uint32_t b1) {
    asm volatile(
        "mma.sync.aligned.m16n8k16.row.col.f32.f16.f16.f32 "
        "{%0,%1,%2,%3},{%4,%5,%6,%7},{%8,%9},{%0,%1,%2,%3};"
        : "+f"(c[0]), "+f"(c[1]), "+f"(c[2]), "+f"(c[3])
        : "r"(a[0]), "r"(a[1]), "r"(a[2]), "r"(a[3]), "r"(b0), "r"(b1));
}
__device__ __forceinline__ uint32_t pkh(__half a, __half b) {
    return (uint32_t)__half_as_ushort(a) | ((uint32_t)__half_as_ushort(b) << 16);
}
__device__ __forceinline__ void split2(float x, float y, uint32_t& hi, uint32_t& lo) {
    __half hx = __float2half_rn(x), hy = __float2half_rn(y);
    hi = pkh(hx, hy);
    lo = pkh(__float2half_rn(x - __half2float(hx)), __float2half_rn(y - __half2float(hy)));
}
__device__ __forceinline__ uint32_t f2h2(float a, float b) {
    __half2 h = __floats2half2_rn(a, b);
    return *(uint32_t*)&h;
}
__device__ __forceinline__ uint32_t h2scale8(uint32_t x) {  // * 0.125 (exact)
    __half2 v = *(__half2*)&x;
    v = __hmul2(v, __float2half2_rn(0.125f));
    return *(uint32_t*)&v;
}

// ---------------- split kernels ---------------------------------------------
__global__ __launch_bounds__(256) void split_zt_kernel(const float* __restrict__ ZT) {
    size_t i = ((size_t)blockIdx.x * blockDim.x + threadIdx.x) * 4;
    float4 v = *(const float4*)(ZT + i);
    uint32_t h0, l0, h1, l1;
    split2(v.x, v.y, h0, l0);
    split2(v.z, v.w, h1, l1);
    *(uint2*)&g_zt_hi[i] = make_uint2(h0, h1);
    *(uint2*)&g_zt_lo[i] = make_uint2(l0, l1);
}

__global__ __launch_bounds__(1024) void split_w_kernel(const float* __restrict__ W) {
    __shared__ float t[32][33];
    int tx = threadIdx.x, ty = threadIdx.y;
    int k = blockIdx.y * 32 + ty, c = blockIdx.x * 32 + tx;
    float v = W[(size_t)k * DIMM + c];
    __half h = __float2half_rn(v);
    g_w_hi[(size_t)k * DIMM + c] = h;
    g_w_lo[(size_t)k * DIMM + c] = __float2half_rn(v - __half2float(h));
    t[ty][tx] = v;
    __syncthreads();
    int k2 = blockIdx.y * 32 + tx, c2 = blockIdx.x * 32 + ty;
    float v2 = t[tx][ty];
    __half h2 = __float2half_rn(v2);
    g_wt_hi[(size_t)c2 * DIMM + k2] = h2;
    g_wt_lo[(size_t)c2 * DIMM + k2] = __float2half_rn(v2 - __half2float(h2));
}

// ---------------- HMMA GEMM (3-stage cp.async pipeline) ---------------------
// C[128x128 tile] = A[128,1024] · B[128,1024]^T, fp16 hi/lo 3-term, fp32 acc.
#define G_TILE_B (128 * S72 * 2)   /* 18432 B per tile */
#define G_STAGE_B (4 * G_TILE_B)   /* Ah,Al,Bh,Bl */
#define GEMM_SMEM (3 * G_STAGE_B)  /* 221184 B */

template <int MODE>
__global__ __launch_bounds__(256) void gemm_hmma(float* __restrict__ outp) {
    extern __shared__ char sm[];
    const uint32_t aS = smem_u32(sm);
    const int tid = threadIdx.x, lane = tid & 31, wid = tid >> 5;
    const int wm = wid & 3, wn = wid >> 2;
    const int bm = blockIdx.y * 128, bn = blockIdx.x * 128;

    const __half* gp0 = ((MODE == 0) ? g_zt_hi : g_ssa_hi) + (size_t)bm * DIMM;
    const __half* gp1 = ((MODE == 0) ? g_zt_lo : g_ssa_lo) + (size_t)bm * DIMM;
    const __half* gp2 = ((MODE == 0) ? g_w_hi : g_wt_hi) + (size_t)bn * DIMM;
    const __half* gp3 = ((MODE == 0) ? g_w_lo : g_wt_lo) + (size_t)bn * DIMM;

    float c[2][8][4];
#pragma unroll
    for (int mi = 0; mi < 2; mi++)
#pragma unroll
        for (int nb = 0; nb < 8; nb++)
#pragma unroll
            for (int q = 0; q < 4; q++) c[mi][nb][q] = 0.f;

    // stage loader: 128 rows x 64 cols = 1024 16B-chunks per tile; 4 tiles.
    auto load_stage = [&](int st, int k0) {
        uint32_t sb = aS + (uint32_t)st * G_STAGE_B;
#pragma unroll
        for (int i = 0; i < 4; i++) {
            int idx = tid + i * 256;
            int r = idx >> 3, cc = (idx & 7) * 8;
            uint32_t so = (uint32_t)(r * S72 + cc) * 2;
            size_t go = (size_t)r * DIMM + k0 + cc;
            cp16(sb + 0 * G_TILE_B + so, gp0 + go);
            cp16(sb + 1 * G_TILE_B + so, gp1 + go);
            cp16(sb + 2 * G_TILE_B + so, gp2 + go);
            cp16(sb + 3 * G_TILE_B + so, gp3 + go);
        }
    };

    load_stage(0, 0);
    CP_COMMIT();

    for (int ch = 0; ch < 16; ch++) {
        if (ch + 1 < 16) {
            load_stage((ch + 1) % 3, (ch + 1) * 64);
            CP_COMMIT();
            CP_WAIT1();
        } else {
            CP_WAIT0();
        }
        __syncthreads();

        const uint32_t sb = aS + (uint32_t)(ch % 3) * G_STAGE_B;
        const uint32_t aAh = sb, aAl = sb + G_TILE_B;
        const uint32_t aBh = sb + 2 * G_TILE_B, aBl = sb + 3 * G_TILE_B;
#pragma unroll
        for (int kd = 0; kd < 4; kd++) {
            const uint32_t colb = (kd * 16 + ((lane >> 4) << 3)) * 2;
            uint32_t ah[2][4], al[2][4];
#pragma unroll
            for (int mi = 0; mi < 2; mi++) {
                uint32_t ro = (uint32_t)(wm * 32 + mi * 16 + (lane & 15)) * 144 + colb;
                ldsm4(ah[mi][0], ah[mi][1], ah[mi][2], ah[mi][3], aAh + ro);
                ldsm4(al[mi][0], al[mi][1], al[mi][2], al[mi][3], aAl + ro);
            }
            uint32_t bh[8][2], bl[8][2];
#pragma unroll
            for (int np = 0; np < 4; np++) {
                uint32_t ro = (uint32_t)(wn * 64 + np * 16 + (lane & 15)) * 144 + colb;
                uint32_t r0, r1, r2, r3;
                ldsm4(r0, r1, r2, r3, aBh + ro);
                bh[np * 2][0] = r0; bh[np * 2][1] = r2;
                bh[np * 2 + 1][0] = r1; bh[np * 2 + 1][1] = r3;
                ldsm4(r0, r1, r2, r3, aBl + ro);
                bl[np * 2][0] = r0; bl[np * 2][1] = r2;
                bl[np * 2 + 1][0] = r1; bl[np * 2 + 1][1] = r3;
            }
#pragma unroll
            for (int mi = 0; mi < 2; mi++)
#pragma unroll
                for (int nb = 0; nb < 8; nb++) {
                    mma16816(c[mi][nb], ah[mi], bh[nb][0], bh[nb][1]);
                    mma16816(c[mi][nb], ah[mi], bl[nb][0], bl[nb][1]);
                    mma16816(c[mi][nb], al[mi], bh[nb][0], bh[nb][1]);
                }
        }
    }

    // epilogue
#pragma unroll
    for (int mi = 0; mi < 2; mi++) {
        const int m0 = bm + wm * 32 + mi * 16 + (lane >> 2);
#pragma unroll
        for (int nb = 0; nb < 8; nb++) {
            const int col = bn + wn * 64 + nb * 8 + 2 * (lane & 3);
            if (MODE == 0) {
                const int h = col >> 6, d = col & 63;
#pragma unroll
                for (int rr = 0; rr < 2; rr++) {
                    int m = m0 + rr * 8;
                    int b = m >> 11, n = m & 2047;
                    size_t base = (((size_t)(b * HH + h) * NN) + n) * DHH + d;
                    uint32_t hi, lo;
                    split2(c[mi][nb][rr * 2], c[mi][nb][rr * 2 + 1], hi, lo);
                    *(uint32_t*)&g_ztu_hi[base] = hi;
                    *(uint32_t*)&g_ztu_lo[base] = lo;
                }
            } else {
                *(float2*)&outp[(size_t)m0 * DIMM + col] = make_float2(c[mi][nb][0], c[mi][nb][1]);
                *(float2*)&outp[(size_t)(m0 + 8) * DIMM + col] = make_float2(c[mi][nb][2], c[mi][nb][3]);
            }
        }
    }
}

// ---------------- HMMA flash attention (3-stage K pipeline) ------------------
// CTA: 128 q rows of one (b,h); 8 warps x m16; key chunks of 64. Q=K=V.
#define A_QTILE_B (128 * S72 * 2)  /* 36864 per (hi or lo) */
#define A_KTILE_B (64 * S72 * 2)   /* 9216 per tile */
#define A_KSTAGE_B (2 * A_KTILE_B) /* h + l */
#define ATTN_SMEM (2 * A_QTILE_B + 3 * A_KSTAGE_B) /* 129024 B */

__global__ __launch_bounds__(256) void attn_hmma() {
    extern __shared__ char sm[];
    const uint32_t aQh = smem_u32(sm);
    const uint32_t aQl = aQh + A_QTILE_B;
    const uint32_t aK0 = aQl + A_QTILE_B;

    const int tid = threadIdx.x, lane = tid & 31, wid = tid >> 5;
    const int bh = blockIdx.y, q0 = blockIdx.x * 128;
    const __half* zh = g_ztu_hi + (size_t)bh * NN * DHH;
    const __half* zl = g_ztu_lo + (size_t)bh * NN * DHH;

    // Q tile -> smem (regular loads, one-time)
    {
        __half* sQh = (__half*)sm;
        __half* sQl = sQh + 128 * S72;
#pragma unroll
        for (int i = 0; i < 4; i++) {
            int idx = tid + i * 256;
            int r = idx >> 3, cc = (idx & 7) * 8;
            *(uint4*)(sQh + r * S72 + cc) = *(const uint4*)(zh + (size_t)(q0 + r) * DHH + cc);
            *(uint4*)(sQl + r * S72 + cc) = *(const uint4*)(zl + (size_t)(q0 + r) * DHH + cc);
        }
    }

    auto load_k = [&](int st, int j0) {
        uint32_t sb = aK0 + (uint32_t)st * A_KSTAGE_B;
#pragma unroll
        for (int i = 0; i < 2; i++) {
            int idx = tid + i * 256;
            int r = idx >> 3, cc = (idx & 7) * 8;
            uint32_t so = (uint32_t)(r * S72 + cc) * 2;
            size_t go = (size_t)(j0 + r) * DHH + cc;
            cp16(sb + so, zh + go);
            cp16(sb + A_KTILE_B + so, zl + go);
        }
    };
    load_k(0, 0);
    CP_COMMIT();
    __syncthreads();  // Q tile visible

    // Q fragments, SCALE folded in (exact: *2^-3)
    uint32_t qh[4][4], ql[4][4];
#pragma unroll
    for (int kd = 0; kd < 4; kd++) {
        uint32_t ro = (uint32_t)(wid * 16 + (lane & 15)) * 144 + (kd * 16 + ((lane >> 4) << 3)) * 2;
        ldsm4(qh[kd][0], qh[kd][1], qh[kd][2], qh[kd][3], aQh + ro);
        ldsm4(ql[kd][0], ql[kd][1], ql[kd][2], ql[kd][3], aQl + ro);
#pragma unroll
        for (int r = 0; r < 4; r++) {
            qh[kd][r] = h2scale8(qh[kd][r]);
            ql[kd][r] = h2scale8(ql[kd][r]);
        }
    }

    float o[8][4];
#pragma unroll
    for (int nb = 0; nb < 8; nb++)
#pragma unroll
        for (int q = 0; q < 4; q++) o[nb][q] = 0.f;
    float mr0 = -INFINITY, mr1 = -INFINITY, l0 = 0.f, l1 = 0.f;

    for (int ch = 0; ch < NN / 64; ch++) {
        if (ch + 1 < NN / 64) {
            load_k((ch + 1) % 3, (ch + 1) * 64);
            CP_COMMIT();
            CP_WAIT1();
        } else {
            CP_WAIT0();
        }
        __syncthreads();

        const uint32_t aKh = aK0 + (uint32_t)(ch % 3) * A_KSTAGE_B;
        const uint32_t aKl = aKh + A_KTILE_B;

        // S = (Q*SCALE) K^T  (16 x 64 per warp)
        float s[8][4];
#pragma unroll
        for (int nb = 0; nb < 8; nb++)
#pragma unroll
            for (int q = 0; q < 4; q++) s[nb][q] = 0.f;
#pragma unroll
        for (int kd = 0; kd < 4; kd++) {
            const uint32_t colb = (kd * 16 + ((lane >> 4) << 3)) * 2;
            uint32_t bhf[8][2], blf[8][2];
#pragma unroll
            for (int np = 0; np < 4; np++) {
                uint32_t ro = (uint32_t)(np * 16 + (lane & 15)) * 144 + colb;
                uint32_t r0, r1, r2, r3;
                ldsm4(r0, r1, r2, r3, aKh + ro);
                bhf[np * 2][0] = r0; bhf[np * 2][1] = r2;
                bhf[np * 2 + 1][0] = r1; bhf[np * 2 + 1][1] = r3;
                ldsm4(r0, r1, r2, r3, aKl + ro);
                blf[np * 2][0] = r0; blf[np * 2][1] = r2;
                blf[np * 2 + 1][0] = r1; blf[np * 2 + 1][1] = r3;
            }
#pragma unroll
            for (int nb = 0; nb < 8; nb++) {
                mma16816(s[nb], qh[kd], bhf[nb][0], bhf[nb][1]);
                mma16816(s[nb], qh[kd], blf[nb][0], blf[nb][1]);
                mma16816(s[nb], ql[kd], bhf[nb][0], bhf[nb][1]);
            }
        }

        // softmax (rows r=lane/4 and r+8)
        float t0 = -INFINITY, t1 = -INFINITY;
#pragma unroll
        for (int nb = 0; nb < 8; nb++) {
            t0 = fmaxf(t0, fmaxf(s[nb][0], s[nb][1]));
            t1 = fmaxf(t1, fmaxf(s[nb][2], s[nb][3]));
        }
        t0 = fmaxf(t0, __shfl_xor_sync(0xffffffffu, t0, 1));
        t0 = fmaxf(t0, __shfl_xor_sync(0xffffffffu, t0, 2));
        t1 = fmaxf(t1, __shfl_xor_sync(0xffffffffu, t1, 1));
        t1 = fmaxf(t1, __shfl_xor_sync(0xffffffffu, t1, 2));
        float mn0 = fmaxf(mr0, t0), mn1 = fmaxf(mr1, t1);
        float al0 = __expf(mr0 - mn0), al1 = __expf(mr1 - mn1);
        float ls0 = 0.f, ls1 = 0.f;
#pragma unroll
        for (int nb = 0; nb < 8; nb++) {
            s[nb][0] = __expf(s[nb][0] - mn0);
            s[nb][1] = __expf(s[nb][1] - mn0);
            s[nb][2] = __expf(s[nb][2] - mn1);
            s[nb][3] = __expf(s[nb][3] - mn1);
            ls0 += s[nb][0] + s[nb][1];
            ls1 += s[nb][2] + s[nb][3];
        }
        ls0 += __shfl_xor_sync(0xffffffffu, ls0, 1);
        ls0 += __shfl_xor_sync(0xffffffffu, ls0, 2);
        ls1 += __shfl_xor_sync(0xffffffffu, ls1, 1);
        ls1 += __shfl_xor_sync(0xffffffffu, ls1, 2);
        l0 = l0 * al0 + ls0;
        l1 = l1 * al1 + ls1;
        mr0 = mn0;
        mr1 = mn1;
#pragma unroll
        for (int nb = 0; nb < 8; nb++) {
            o[nb][0] *= al0; o[nb][1] *= al0;
            o[nb][2] *= al1; o[nb][3] *= al1;
        }

        // O += P_hi (V_hi + V_lo)   (V = same K tile, ldmatrix.trans)
#pragma unroll
        for (int kj = 0; kj < 4; kj++) {
            uint32_t pah[4];
            pah[0] = f2h2(s[2 * kj][0], s[2 * kj][1]);
            pah[1] = f2h2(s[2 * kj][2], s[2 * kj][3]);
            pah[2] = f2h2(s[2 * kj + 1][0], s[2 * kj + 1][1]);
            pah[3] = f2h2(s[2 * kj + 1][2], s[2 * kj + 1][3]);

            const uint32_t colb = ((lane >> 4) << 3) * 2;
            uint32_t vh[8][2], vl[8][2];
#pragma unroll
            for (int dp = 0; dp < 4; dp++) {
                uint32_t ro = (uint32_t)(kj * 16 + (lane & 15)) * 144 + dp * 32 + colb;
                uint32_t r0, r1, r2, r3;
                ldsm4t(r0, r1, r2, r3, aKh + ro);
                vh[dp * 2][0] = r0; vh[dp * 2][1] = r1;
                vh[dp * 2 + 1][0] = r2; vh[dp * 2 + 1][1] = r3;
                ldsm4t(r0, r1, r2, r3, aKl + ro);
                vl[dp * 2][0] = r0; vl[dp * 2][1] = r1;
                vl[dp * 2 + 1][0] = r2; vl[dp * 2 + 1][1] = r3;
            }
#pragma unroll
            for (int db = 0; db < 8; db++) {
                mma16816(o[db], pah, vh[db][0], vh[db][1]);
                mma16816(o[db], pah, vl[db][0], vl[db][1]);
            }
        }
    }

    // epilogue -> ssa hi/lo [b, n, h*64+d]
    const float inv0 = 1.f / l0, inv1 = 1.f / l1;
    const int b = bh >> 4, h = bh & 15;
    const int r0w = q0 + wid * 16 + (lane >> 2);
#pragma unroll
    for (int db = 0; db < 8; db++) {
        const int d = db * 8 + 2 * (lane & 3);
        size_t base0 = ((size_t)b * NN + r0w) * DIMM + h * DHH + d;
        size_t base1 = ((size_t)b * NN + r0w + 8) * DIMM + h * DHH + d;
        uint32_t hi, lo;
        split2(o[db][0] * inv0, o[db][1] * inv0, hi, lo);
        *(uint32_t*)&g_ssa_hi[base0] = hi;
        *(uint32_t*)&g_ssa_lo[base0] = lo;
        split2(o[db][2] * inv1, o[db][3] * inv1, hi, lo);
        *(uint32_t*)&g_ssa_hi[base1] = hi;
        *(uint32_t*)&g_ssa_lo[base1] = lo;
    }
}

// ---------------- launch -----------------------------------------------------
extern "C" void kernel_launch(void* const* d_in, const int* in_sizes, int n_in,
                              void* d_out, int out_size) {
    const float* ZT = (const float*)d_in[0];  // [B, N, DIM]
    const float* W = (const float*)d_in[1];   // [H*DH, DIM]
    float* out = (float*)d_out;               // [B, N, DIM]
    (void)in_sizes; (void)n_in; (void)out_size;

    cudaFuncSetAttribute(gemm_hmma<0>, cudaFuncAttributeMaxDynamicSharedMemorySize, GEMM_SMEM);
    cudaFuncSetAttribute(gemm_hmma<1>, cudaFuncAttributeMaxDynamicSharedMemorySize, GEMM_SMEM);
    cudaFuncSetAttribute(attn_hmma, cudaFuncAttributeMaxDynamicSharedMemorySize, ATTN_SMEM);

    split_zt_kernel<<<(MTOT * DIMM) / (256 * 4), 256>>>(ZT);
    split_w_kernel<<<dim3(32, 32), dim3(32, 32)>>>(W);
    gemm_hmma<0><<<dim3(DIMM / 128, MTOT / 128), 256, GEMM_SMEM>>>(nullptr);
    attn_hmma<<<dim3(NN / 128, BB * HH), 256, ATTN_SMEM>>>();
    gemm_hmma<1><<<dim3(DIMM / 128, MTOT / 128), 256, GEMM_SMEM>>>(out);
}